// round 7
// baseline (speedup 1.0000x reference)
#include <cuda_runtime.h>
#include <cstdint>

#define BATCH 32
#define CCH   256
#define HW    1024
#define TM 128
#define TN 128
#define KT 16
#define RS2 132                       // smem row stride in float2 (128 + 4 pad)
#define TILE2 (KT * RS2)              // float2 per operand tile (2112)
#define BUF2  (2 * TILE2)             // float2 per buffer (A + B)
#define SMEM_DYN (2 * BUF2 * 8)       // bytes: 2 buffers
#define INV_T 14.285714285714286f

__device__ float2   g_Ai[(size_t)BATCH * CCH * HW];   // (hi, lo) interleaved
__device__ float2   g_Bi[(size_t)BATCH * CCH * HW];
__device__ float    g_M [(size_t)BATCH * HW * HW];
__device__ unsigned g_maxIk[BATCH * HW];
__device__ unsigned g_maxJk[BATCH * HW];
__device__ float    g_sumI[BATCH * HW];
__device__ float    g_sumJ[BATCH * HW];

__device__ __forceinline__ unsigned fkey(float f) {
    unsigned u = __float_as_uint(f);
    return u ^ ((unsigned)(((int)u) >> 31) | 0x80000000u);
}
__device__ __forceinline__ float kdec(unsigned k) {
    unsigned u = (k & 0x80000000u) ? (k ^ 0x80000000u) : ~k;
    return __uint_as_float(u);
}
__device__ __forceinline__ uint32_t smem_u32(const void* p) {
    uint32_t a;
    asm("{ .reg .u64 t; cvta.to.shared.u64 t, %1; cvt.u32.u64 %0, t; }" : "=r"(a) : "l"(p));
    return a;
}
__device__ __forceinline__ void tf32_split(float v, float& hi, float& lo) {
    uint32_t hv; asm("cvt.rna.tf32.f32 %0, %1;" : "=r"(hv) : "f"(v));
    hi = __uint_as_float(hv);
    float r = v - hi;
    uint32_t lv; asm("cvt.rna.tf32.f32 %0, %1;" : "=r"(lv) : "f"(r));
    lo = __uint_as_float(lv);
}
__device__ __forceinline__ void cp16(uint32_t dst, const void* src) {
    asm volatile("cp.async.cg.shared.global [%0], [%1], 16;" :: "r"(dst), "l"(src));
}
#define CP_COMMIT() asm volatile("cp.async.commit_group;" ::: "memory")
#define CP_WAIT1()  asm volatile("cp.async.wait_group 1;" ::: "memory")

__device__ __forceinline__ void mma8(float* c, const unsigned* a, const unsigned* b) {
    asm volatile(
        "mma.sync.aligned.m16n8k8.row.col.f32.tf32.tf32.f32 "
        "{%0,%1,%2,%3}, {%4,%5,%6,%7}, {%8,%9}, {%0,%1,%2,%3};"
        : "+f"(c[0]), "+f"(c[1]), "+f"(c[2]), "+f"(c[3])
        : "r"(a[0]), "r"(a[1]), "r"(a[2]), "r"(a[3]), "r"(b[0]), "r"(b[1]));
}

// ---------------- K0: reset ----------------
__global__ void k_init() {
    int idx = blockIdx.x * blockDim.x + threadIdx.x;
    if (idx < BATCH * HW) {
        g_maxIk[idx] = 0u;
        g_maxJk[idx] = 0u;
        g_sumI[idx]  = 0.f;
    }
}

// ---------------- K1: transpose A (h,w)->(j=w*32+h) + split, interleaved out ----
__global__ __launch_bounds__(256) void k_transA(const float* __restrict__ A) {
    __shared__ float s[32][33];
    const size_t plane = blockIdx.x;                 // b*C + c
    const float* Ap = A + plane * 1024;
    float2* Op = g_Ai + plane * 1024;
    const int t = threadIdx.x;
#pragma unroll
    for (int l = 0; l < 4; l++) { int idx = t + l * 256; s[idx >> 5][idx & 31] = Ap[idx]; }
    __syncthreads();
#pragma unroll
    for (int l = 0; l < 4; l++) {
        int idx = t + l * 256;
        float hi, lo;
        tf32_split(s[idx & 31][idx >> 5], hi, lo);
        Op[idx] = make_float2(hi, lo);
    }
}

// ---------------- K2: elementwise split of B, interleaved out ----------------
__global__ __launch_bounds__(256) void k_splitB(const float* __restrict__ B) {
    size_t idx = ((size_t)blockIdx.x * 256 + threadIdx.x) * 4;
    float4 v = *(const float4*)(B + idx);
    float4 o0, o1;
    tf32_split(v.x, o0.x, o0.y); tf32_split(v.y, o0.z, o0.w);
    tf32_split(v.z, o1.x, o1.y); tf32_split(v.w, o1.z, o1.w);
    *(float4*)(g_Bi + idx)     = o0;
    *(float4*)(g_Bi + idx + 2) = o1;
}

// ---------------- K3: mma.sync tf32 3-split GEMM + tile maxes ----------------
__device__ __forceinline__ void fill_buf(uint32_t bufA, uint32_t bufB, int k0,
                                         const float2* pA, const float2* pB, int t) {
#pragma unroll
    for (int l = 0; l < 4; l++) {
        int idx = t + 256 * l;
        int r = idx >> 6, c = idx & 63;            // row 0..15, 16B-chunk 0..63
        uint32_t so = (uint32_t)(r * RS2 * 8 + c * 16);
        size_t go = (size_t)(k0 + r) * HW + c * 2;
        cp16(bufA + so, pA + go);
        cp16(bufB + so, pB + go);
    }
}

__global__ __launch_bounds__(256) void k_gemm_mma() {
    extern __shared__ float dsm[];
    __shared__ unsigned rowk[TM], colk[TN];
    const uint32_t sb = smem_u32(dsm);

    const int t = threadIdx.x;
    const int b = blockIdx.z, i0 = blockIdx.x * TN, j0 = blockIdx.y * TM;
    const int wid = t >> 5, lane = t & 31;
    const int wm = wid >> 1, wn = wid & 1;           // 4 x 2 warps
    const int g = lane >> 2, tig = lane & 3;

    if (t < TM) rowk[t] = 0u;
    if (t < TN) colk[t] = 0u;

    const float2* pA = g_Ai + (size_t)b * CCH * HW + j0;
    const float2* pB = g_Bi + (size_t)b * CCH * HW + i0;

    float c[2][8][4];
#pragma unroll
    for (int mt = 0; mt < 2; mt++)
#pragma unroll
        for (int nt = 0; nt < 8; nt++)
#pragma unroll
            for (int q = 0; q < 4; q++) c[mt][nt][q] = 0.f;

    fill_buf(sb, sb + TILE2 * 8, 0, pA, pB, t);
    CP_COMMIT();
    fill_buf(sb + BUF2 * 8, sb + (BUF2 + TILE2) * 8, KT, pA, pB, t);
    CP_COMMIT();

    for (int k = 0; k < CCH / KT; k++) {
        const int p = k & 1;
        const float2* sA2 = (const float2*)dsm + (size_t)p * BUF2;
        const float2* sB2 = sA2 + TILE2;
        CP_WAIT1();
        __syncthreads();
#pragma unroll
        for (int kk = 0; kk < KT; kk += 8) {
            unsigned ah[2][4], al[2][4], bh[8][2], bl[8][2];
#pragma unroll
            for (int mt = 0; mt < 2; mt++) {
                const int m = wm * 32 + mt * 16 + g;
                float2 v0 = sA2[(kk + tig) * RS2 + m];
                float2 v1 = sA2[(kk + tig) * RS2 + m + 8];
                float2 v2 = sA2[(kk + tig + 4) * RS2 + m];
                float2 v3 = sA2[(kk + tig + 4) * RS2 + m + 8];
                ah[mt][0] = __float_as_uint(v0.x); al[mt][0] = __float_as_uint(v0.y);
                ah[mt][1] = __float_as_uint(v1.x); al[mt][1] = __float_as_uint(v1.y);
                ah[mt][2] = __float_as_uint(v2.x); al[mt][2] = __float_as_uint(v2.y);
                ah[mt][3] = __float_as_uint(v3.x); al[mt][3] = __float_as_uint(v3.y);
            }
#pragma unroll
            for (int nt = 0; nt < 8; nt++) {
                const int n = wn * 64 + nt * 8 + g;
                float2 w0 = sB2[(kk + tig) * RS2 + n];
                float2 w1 = sB2[(kk + tig + 4) * RS2 + n];
                bh[nt][0] = __float_as_uint(w0.x); bl[nt][0] = __float_as_uint(w0.y);
                bh[nt][1] = __float_as_uint(w1.x); bl[nt][1] = __float_as_uint(w1.y);
            }
            // product-major: 16 independent accumulator chains between reuses
#pragma unroll
            for (int mt = 0; mt < 2; mt++)
#pragma unroll
                for (int nt = 0; nt < 8; nt++) mma8(c[mt][nt], ah[mt], bh[nt]);
#pragma unroll
            for (int mt = 0; mt < 2; mt++)
#pragma unroll
                for (int nt = 0; nt < 8; nt++) mma8(c[mt][nt], ah[mt], bl[nt]);
#pragma unroll
            for (int mt = 0; mt < 2; mt++)
#pragma unroll
                for (int nt = 0; nt < 8; nt++) mma8(c[mt][nt], al[mt], bh[nt]);
        }
        __syncthreads();
        if (k + 2 < CCH / KT)
            fill_buf(sb + p * BUF2 * 8, sb + (p * BUF2 + TILE2) * 8,
                     (k + 2) * KT, pA, pB, t);
        CP_COMMIT();
    }

    // scale
#pragma unroll
    for (int mt = 0; mt < 2; mt++)
#pragma unroll
        for (int nt = 0; nt < 8; nt++)
#pragma unroll
            for (int q = 0; q < 4; q++) c[mt][nt][q] *= INV_T;

    // store G
#pragma unroll
    for (int mt = 0; mt < 2; mt++)
#pragma unroll
        for (int hb = 0; hb < 2; hb++) {
            const int j = j0 + wm * 32 + mt * 16 + g + 8 * hb;
            float* rowp = g_M + ((size_t)b * HW + j) * HW + i0 + wn * 64;
#pragma unroll
            for (int nt = 0; nt < 8; nt++)
                *(float2*)(rowp + nt * 8 + tig * 2) =
                    make_float2(c[mt][nt][2 * hb], c[mt][nt][2 * hb + 1]);
        }

    // row maxes (reduce across tig quad)
#pragma unroll
    for (int mt = 0; mt < 2; mt++)
#pragma unroll
        for (int hb = 0; hb < 2; hb++) {
            float m = -3.0e38f;
#pragma unroll
            for (int nt = 0; nt < 8; nt++)
                m = fmaxf(m, fmaxf(c[mt][nt][2 * hb], c[mt][nt][2 * hb + 1]));
#pragma unroll
            for (int o = 1; o < 4; o <<= 1)
                m = fmaxf(m, __shfl_xor_sync(0xffffffffu, m, o));
            if (tig == 0) atomicMax(&rowk[wm * 32 + mt * 16 + g + 8 * hb], fkey(m));
        }
    // col maxes (reduce across g: lanes stride 4)
#pragma unroll
    for (int nt = 0; nt < 8; nt++)
#pragma unroll
        for (int par = 0; par < 2; par++) {
            float m = fmaxf(fmaxf(c[0][nt][par], c[0][nt][2 + par]),
                            fmaxf(c[1][nt][par], c[1][nt][2 + par]));
#pragma unroll
            for (int o = 4; o < 32; o <<= 1)
                m = fmaxf(m, __shfl_xor_sync(0xffffffffu, m, o));
            if (g == 0) atomicMax(&colk[wn * 64 + nt * 8 + tig * 2 + par], fkey(m));
        }
    __syncthreads();
    if (t < TM) atomicMax(&g_maxJk[b * HW + j0 + t], rowk[t]);
    if (t < TN) atomicMax(&g_maxIk[b * HW + i0 + t], colk[t]);
}

// ---------------- K4: stats — CTA covers 128 rows x ALL cols ----------------
__global__ __launch_bounds__(256) void k_stats() {
    __shared__ float sI[8][1024];
    const int b = blockIdx.y, j0 = blockIdx.x * 128;
    const int t = threadIdx.x, w = t >> 5, lane = t & 31;

    float mIv[32], accI[32];
#pragma unroll
    for (int q = 0; q < 8; q++)
#pragma unroll
        for (int s = 0; s < 4; s++) {
            mIv[q * 4 + s] = kdec(g_maxIk[b * HW + q * 128 + lane * 4 + s]);
            accI[q * 4 + s] = 0.f;
        }

    for (int r = 0; r < 16; r++) {
        const int row = j0 + w + 8 * r;
        const float mJ = kdec(g_maxJk[b * HW + row]);
        const float* Gp = g_M + ((size_t)b * HW + row) * HW;
        float accJ = 0.f;
#pragma unroll
        for (int q = 0; q < 8; q++) {
            float4 v = *(const float4*)(Gp + q * 128 + lane * 4);
            accJ += __expf(v.x - mJ) + __expf(v.y - mJ) +
                    __expf(v.z - mJ) + __expf(v.w - mJ);
            accI[q * 4 + 0] += __expf(v.x - mIv[q * 4 + 0]);
            accI[q * 4 + 1] += __expf(v.y - mIv[q * 4 + 1]);
            accI[q * 4 + 2] += __expf(v.z - mIv[q * 4 + 2]);
            accI[q * 4 + 3] += __expf(v.w - mIv[q * 4 + 3]);
        }
#pragma unroll
        for (int o = 16; o > 0; o >>= 1) accJ += __shfl_xor_sync(0xffffffffu, accJ, o);
        if (lane == 0) g_sumJ[b * HW + row] = accJ;   // full row in one CTA
    }
#pragma unroll
    for (int q = 0; q < 8; q++)
#pragma unroll
        for (int s = 0; s < 4; s++) sI[w][q * 128 + lane * 4 + s] = accI[q * 4 + s];
    __syncthreads();
#pragma unroll
    for (int col = t; col < 1024; col += 256) {
        float s = 0.f;
#pragma unroll
        for (int ww = 0; ww < 8; ww++) s += sI[ww][col];
        atomicAdd(&g_sumI[b * HW + col], s);
    }
}

// ---------------- K5: out = exp(2G - mI - mJ) / (sI*sJ), vectorized ----------------
__global__ __launch_bounds__(256) void k_final(float* __restrict__ out) {
    __shared__ float mI[128], mJ[128], rI[128], rJ[128];
    const int b = blockIdx.z, i0 = blockIdx.x * 128, j0 = blockIdx.y * 128;
    const int t = threadIdx.x;
    if (t < 128) {
        mI[t] = kdec(g_maxIk[b * HW + i0 + t]);
        mJ[t] = kdec(g_maxJk[b * HW + j0 + t]);
        rI[t] = 1.0f / g_sumI[b * HW + i0 + t];
        rJ[t] = 1.0f / g_sumJ[b * HW + j0 + t];
    }
    __syncthreads();
    const float* Gp = g_M + ((size_t)b * HW + j0) * HW + i0;
    float*       Op = out + ((size_t)b * HW + j0) * HW + i0;
#pragma unroll 2
    for (int idx = t; idx < 128 * 32; idx += 256) {
        const int jj = idx >> 5, i4 = (idx & 31) * 4;
        float4 v = *(const float4*)(Gp + (size_t)jj * HW + i4);
        const float mj = mJ[jj], rj = rJ[jj];
        float4 o;
        o.x = __expf(2.f * v.x - mI[i4 + 0] - mj) * rI[i4 + 0] * rj;
        o.y = __expf(2.f * v.y - mI[i4 + 1] - mj) * rI[i4 + 1] * rj;
        o.z = __expf(2.f * v.z - mI[i4 + 2] - mj) * rI[i4 + 2] * rj;
        o.w = __expf(2.f * v.w - mI[i4 + 3] - mj) * rI[i4 + 3] * rj;
        *(float4*)(Op + (size_t)jj * HW + i4) = o;
    }
}

// ---------------- launch ----------------
extern "C" void kernel_launch(void* const* d_in, const int* in_sizes, int n_in,
                              void* d_out, int out_size) {
    const float* A  = (const float*)d_in[0];
    const float* Bf = (const float*)d_in[1];
    float* out = (float*)d_out;

    cudaFuncSetAttribute(k_gemm_mma, cudaFuncAttributeMaxDynamicSharedMemorySize, SMEM_DYN);

    k_init<<<(BATCH * HW + 255) / 256, 256>>>();
    k_transA<<<BATCH * CCH, 256>>>(A);
    k_splitB<<<(BATCH * CCH * HW) / 1024, 256>>>(Bf);
    dim3 ggrid(HW / TN, HW / TM, BATCH);
    k_gemm_mma<<<ggrid, 256, SMEM_DYN>>>();
    dim3 sgrid(HW / 128, BATCH);
    k_stats<<<sgrid, 256>>>();
    dim3 fgrid(HW / 128, HW / 128, BATCH);
    k_final<<<fgrid, 256>>>(out);
}

// round 9
// speedup vs baseline: 1.3281x; 1.3281x over previous
#include <cuda_runtime.h>
#include <cstdint>

#define BATCH 32
#define CCH   256
#define HW    1024
#define TM 128
#define TN 128
#define KT 16
#define RS 136                       // smem row stride (floats): conflict-free frags
#define ABYTES (KT * RS * 4)         // 8704 B per operand array
#define BUFB   (4 * ABYTES)          // 34816 B per buffer (Ah, Al, Bh, Bl)
#define SMEM_DYN (2 * BUFB)
#define INV_T 14.285714285714286f

__device__ float    g_Ah[(size_t)BATCH * CCH * HW];
__device__ float    g_Al[(size_t)BATCH * CCH * HW];
__device__ float    g_Bh[(size_t)BATCH * CCH * HW];
__device__ float    g_Bl[(size_t)BATCH * CCH * HW];
__device__ float    g_M [(size_t)BATCH * HW * HW];
__device__ unsigned g_maxIk[BATCH * HW];
__device__ unsigned g_maxJk[BATCH * HW];
__device__ float    g_sumI[BATCH * HW];
__device__ float    g_sumJ[BATCH * HW];

__device__ __forceinline__ unsigned fkey(float f) {
    unsigned u = __float_as_uint(f);
    return u ^ ((unsigned)(((int)u) >> 31) | 0x80000000u);
}
__device__ __forceinline__ float kdec(unsigned k) {
    unsigned u = (k & 0x80000000u) ? (k ^ 0x80000000u) : ~k;
    return __uint_as_float(u);
}
__device__ __forceinline__ uint32_t smem_u32(const void* p) {
    uint32_t a;
    asm("{ .reg .u64 t; cvta.to.shared.u64 t, %1; cvt.u32.u64 %0, t; }" : "=r"(a) : "l"(p));
    return a;
}
__device__ __forceinline__ void tf32_split(float v, float& hi, float& lo) {
    uint32_t hv; asm("cvt.rna.tf32.f32 %0, %1;" : "=r"(hv) : "f"(v));
    hi = __uint_as_float(hv);
    float r = v - hi;
    uint32_t lv; asm("cvt.rna.tf32.f32 %0, %1;" : "=r"(lv) : "f"(r));
    lo = __uint_as_float(lv);
}
__device__ __forceinline__ void cp16(uint32_t dst, const float* src) {
    asm volatile("cp.async.cg.shared.global [%0], [%1], 16;" :: "r"(dst), "l"(src));
}
#define CP_COMMIT() asm volatile("cp.async.commit_group;" ::: "memory")
#define CP_WAIT1()  asm volatile("cp.async.wait_group 1;" ::: "memory")

__device__ __forceinline__ void mma8(float* c, const unsigned* a, const unsigned* b) {
    asm volatile(
        "mma.sync.aligned.m16n8k8.row.col.f32.tf32.tf32.f32 "
        "{%0,%1,%2,%3}, {%4,%5,%6,%7}, {%8,%9}, {%0,%1,%2,%3};"
        : "+f"(c[0]), "+f"(c[1]), "+f"(c[2]), "+f"(c[3])
        : "r"(a[0]), "r"(a[1]), "r"(a[2]), "r"(a[3]), "r"(b[0]), "r"(b[1]));
}

// ---------------- K0: reset ----------------
__global__ void k_init() {
    int idx = blockIdx.x * blockDim.x + threadIdx.x;
    if (idx < BATCH * HW) {
        g_maxIk[idx] = 0u;
        g_maxJk[idx] = 0u;
        g_sumI[idx]  = 0.f;
    }
}

// ---------------- K1: transpose A (h,w)->(j=w*32+h) fused with tf32 split ----------
__global__ __launch_bounds__(256) void k_transA(const float* __restrict__ A) {
    __shared__ float s[32][33];
    const size_t plane = blockIdx.x;                 // b*C + c
    const float* Ap = A + plane * 1024;
    float* Oh = g_Ah + plane * 1024;
    float* Ol = g_Al + plane * 1024;
    const int t = threadIdx.x;
#pragma unroll
    for (int l = 0; l < 4; l++) { int idx = t + l * 256; s[idx >> 5][idx & 31] = Ap[idx]; }
    __syncthreads();
#pragma unroll
    for (int l = 0; l < 4; l++) {
        int idx = t + l * 256;
        float hi, lo;
        tf32_split(s[idx & 31][idx >> 5], hi, lo);
        Oh[idx] = hi; Ol[idx] = lo;
    }
}

// ---------------- K2: elementwise tf32 split of B ----------------
__global__ __launch_bounds__(256) void k_splitB(const float* __restrict__ B) {
    size_t idx = ((size_t)blockIdx.x * 256 + threadIdx.x) * 4;
    float4 v = *(const float4*)(B + idx);
    float4 h, l;
    tf32_split(v.x, h.x, l.x); tf32_split(v.y, h.y, l.y);
    tf32_split(v.z, h.z, l.z); tf32_split(v.w, h.w, l.w);
    *(float4*)(g_Bh + idx) = h;
    *(float4*)(g_Bl + idx) = l;
}

// ---------------- K3: mma.sync tf32 3-split GEMM + tile maxes ----------------
__device__ __forceinline__ void fill_buf(uint32_t buf, int k0,
                                         const float* pAh, const float* pAl,
                                         const float* pBh, const float* pBl, int t) {
#pragma unroll
    for (int l = 0; l < 2; l++) {
        int f4 = t + 256 * l;
        int r = f4 >> 5, c4 = f4 & 31;
        uint32_t so = (uint32_t)(r * RS + c4 * 4) * 4u;
        size_t go = (size_t)(k0 + r) * HW + c4 * 4;
        cp16(buf + 0 * ABYTES + so, pAh + go);
        cp16(buf + 1 * ABYTES + so, pAl + go);
        cp16(buf + 2 * ABYTES + so, pBh + go);
        cp16(buf + 3 * ABYTES + so, pBl + go);
    }
}

__global__ __launch_bounds__(256, 2) void k_gemm_mma() {
    extern __shared__ float dsm[];
    __shared__ unsigned rowk[TM], colk[TN];
    const uint32_t sb = smem_u32(dsm);

    const int t = threadIdx.x;
    const int b = blockIdx.z, i0 = blockIdx.x * TN, j0 = blockIdx.y * TM;
    const int wid = t >> 5, lane = t & 31;
    const int wm = wid >> 1, wn = wid & 1;           // 4 x 2 warps
    const int g = lane >> 2, tig = lane & 3;

    if (t < TM) rowk[t] = 0u;
    if (t < TN) colk[t] = 0u;

    const float* pAh = g_Ah + (size_t)b * CCH * HW + j0;
    const float* pAl = g_Al + (size_t)b * CCH * HW + j0;
    const float* pBh = g_Bh + (size_t)b * CCH * HW + i0;
    const float* pBl = g_Bl + (size_t)b * CCH * HW + i0;

    float c[2][8][4];
#pragma unroll
    for (int mt = 0; mt < 2; mt++)
#pragma unroll
        for (int nt = 0; nt < 8; nt++)
#pragma unroll
            for (int q = 0; q < 4; q++) c[mt][nt][q] = 0.f;

    fill_buf(sb, 0, pAh, pAl, pBh, pBl, t);
    CP_COMMIT();
    fill_buf(sb + BUFB, KT, pAh, pAl, pBh, pBl, t);
    CP_COMMIT();

    for (int k = 0; k < CCH / KT; k++) {
        const int p = k & 1;
        const float* s0 = dsm + p * (BUFB / 4);
        const float* sAh = s0;
        const float* sAl = s0 + ABYTES / 4;
        const float* sBh = s0 + 2 * (ABYTES / 4);
        const float* sBl = s0 + 3 * (ABYTES / 4);
        CP_WAIT1();
        __syncthreads();
#pragma unroll
        for (int kk = 0; kk < KT; kk += 8) {
            unsigned ah[2][4], al[2][4], bh[8][2], bl[8][2];
#pragma unroll
            for (int mt = 0; mt < 2; mt++) {
                const int m = wm * 32 + mt * 16 + g;
                ah[mt][0] = __float_as_uint(sAh[(kk + tig) * RS + m]);
                ah[mt][1] = __float_as_uint(sAh[(kk + tig) * RS + m + 8]);
                ah[mt][2] = __float_as_uint(sAh[(kk + tig + 4) * RS + m]);
                ah[mt][3] = __float_as_uint(sAh[(kk + tig + 4) * RS + m + 8]);
                al[mt][0] = __float_as_uint(sAl[(kk + tig) * RS + m]);
                al[mt][1] = __float_as_uint(sAl[(kk + tig) * RS + m + 8]);
                al[mt][2] = __float_as_uint(sAl[(kk + tig + 4) * RS + m]);
                al[mt][3] = __float_as_uint(sAl[(kk + tig + 4) * RS + m + 8]);
            }
#pragma unroll
            for (int nt = 0; nt < 8; nt++) {
                const int n = wn * 64 + nt * 8 + g;
                bh[nt][0] = __float_as_uint(sBh[(kk + tig) * RS + n]);
                bh[nt][1] = __float_as_uint(sBh[(kk + tig + 4) * RS + n]);
            }
            // pass 1 + 2: bh consumers (16 independent chains each)
#pragma unroll
            for (int mt = 0; mt < 2; mt++)
#pragma unroll
                for (int nt = 0; nt < 8; nt++) mma8(c[mt][nt], ah[mt], bh[nt]);
#pragma unroll
            for (int mt = 0; mt < 2; mt++)
#pragma unroll
                for (int nt = 0; nt < 8; nt++) mma8(c[mt][nt], al[mt], bh[nt]);
            // pass 3: bl consumers (bh dead by here)
#pragma unroll
            for (int nt = 0; nt < 8; nt++) {
                const int n = wn * 64 + nt * 8 + g;
                bl[nt][0] = __float_as_uint(sBl[(kk + tig) * RS + n]);
                bl[nt][1] = __float_as_uint(sBl[(kk + tig + 4) * RS + n]);
            }
#pragma unroll
            for (int mt = 0; mt < 2; mt++)
#pragma unroll
                for (int nt = 0; nt < 8; nt++) mma8(c[mt][nt], ah[mt], bl[nt]);
        }
        __syncthreads();
        if (k + 2 < CCH / KT)
            fill_buf(sb + p * BUFB, (k + 2) * KT, pAh, pAl, pBh, pBl, t);
        CP_COMMIT();
    }

    // scale
#pragma unroll
    for (int mt = 0; mt < 2; mt++)
#pragma unroll
        for (int nt = 0; nt < 8; nt++)
#pragma unroll
            for (int q = 0; q < 4; q++) c[mt][nt][q] *= INV_T;

    // store G: float2 per (mt, hb, nt)
#pragma unroll
    for (int mt = 0; mt < 2; mt++)
#pragma unroll
        for (int hb = 0; hb < 2; hb++) {
            const int j = j0 + wm * 32 + mt * 16 + g + 8 * hb;
            float* rowp = g_M + ((size_t)b * HW + j) * HW + i0 + wn * 64;
#pragma unroll
            for (int nt = 0; nt < 8; nt++)
                *(float2*)(rowp + nt * 8 + tig * 2) =
                    make_float2(c[mt][nt][2 * hb], c[mt][nt][2 * hb + 1]);
        }

    // row maxes (reduce across tig quad)
#pragma unroll
    for (int mt = 0; mt < 2; mt++)
#pragma unroll
        for (int hb = 0; hb < 2; hb++) {
            float m = -3.0e38f;
#pragma unroll
            for (int nt = 0; nt < 8; nt++)
                m = fmaxf(m, fmaxf(c[mt][nt][2 * hb], c[mt][nt][2 * hb + 1]));
#pragma unroll
            for (int o = 1; o < 4; o <<= 1)
                m = fmaxf(m, __shfl_xor_sync(0xffffffffu, m, o));
            if (tig == 0) atomicMax(&rowk[wm * 32 + mt * 16 + g + 8 * hb], fkey(m));
        }
    // col maxes (reduce across g: lanes stride 4)
#pragma unroll
    for (int nt = 0; nt < 8; nt++)
#pragma unroll
        for (int par = 0; par < 2; par++) {
            float m = fmaxf(fmaxf(c[0][nt][par], c[0][nt][2 + par]),
                            fmaxf(c[1][nt][par], c[1][nt][2 + par]));
#pragma unroll
            for (int o = 4; o < 32; o <<= 1)
                m = fmaxf(m, __shfl_xor_sync(0xffffffffu, m, o));
            if (g == 0) atomicMax(&colk[wn * 64 + nt * 8 + tig * 2 + par], fkey(m));
        }
    __syncthreads();
    if (t < TM) atomicMax(&g_maxJk[b * HW + j0 + t], rowk[t]);
    if (t < TN) atomicMax(&g_maxIk[b * HW + i0 + t], colk[t]);
}

// ---------------- K4: stats — CTA covers 128 rows x ALL cols ----------------
__global__ __launch_bounds__(256) void k_stats() {
    __shared__ float sI[8][1024];
    const int b = blockIdx.y, j0 = blockIdx.x * 128;
    const int t = threadIdx.x, w = t >> 5, lane = t & 31;

    float mIv[32], accI[32];
#pragma unroll
    for (int q = 0; q < 8; q++)
#pragma unroll
        for (int s = 0; s < 4; s++) {
            mIv[q * 4 + s] = kdec(g_maxIk[b * HW + q * 128 + lane * 4 + s]);
            accI[q * 4 + s] = 0.f;
        }

    for (int r = 0; r < 16; r++) {
        const int row = j0 + w + 8 * r;
        const float mJ = kdec(g_maxJk[b * HW + row]);
        const float* Gp = g_M + ((size_t)b * HW + row) * HW;
        float accJ = 0.f;
#pragma unroll
        for (int q = 0; q < 8; q++) {
            float4 v = *(const float4*)(Gp + q * 128 + lane * 4);
            accJ += __expf(v.x - mJ) + __expf(v.y - mJ) +
                    __expf(v.z - mJ) + __expf(v.w - mJ);
            accI[q * 4 + 0] += __expf(v.x - mIv[q * 4 + 0]);
            accI[q * 4 + 1] += __expf(v.y - mIv[q * 4 + 1]);
            accI[q * 4 + 2] += __expf(v.z - mIv[q * 4 + 2]);
            accI[q * 4 + 3] += __expf(v.w - mIv[q * 4 + 3]);
        }
#pragma unroll
        for (int o = 16; o > 0; o >>= 1) accJ += __shfl_xor_sync(0xffffffffu, accJ, o);
        if (lane == 0) g_sumJ[b * HW + row] = accJ;   // full row in one CTA
    }
#pragma unroll
    for (int q = 0; q < 8; q++)
#pragma unroll
        for (int s = 0; s < 4; s++) sI[w][q * 128 + lane * 4 + s] = accI[q * 4 + s];
    __syncthreads();
#pragma unroll
    for (int col = t; col < 1024; col += 256) {
        float s = 0.f;
#pragma unroll
        for (int ww = 0; ww < 8; ww++) s += sI[ww][col];
        atomicAdd(&g_sumI[b * HW + col], s);
    }
}

// ---------------- K5: out = exp(2G - mI - mJ) / (sI*sJ), vectorized ----------------
__global__ __launch_bounds__(256) void k_final(float* __restrict__ out) {
    __shared__ float mI[128], mJ[128], rI[128], rJ[128];
    const int b = blockIdx.z, i0 = blockIdx.x * 128, j0 = blockIdx.y * 128;
    const int t = threadIdx.x;
    if (t < 128) {
        mI[t] = kdec(g_maxIk[b * HW + i0 + t]);
        mJ[t] = kdec(g_maxJk[b * HW + j0 + t]);
        rI[t] = 1.0f / g_sumI[b * HW + i0 + t];
        rJ[t] = 1.0f / g_sumJ[b * HW + j0 + t];
    }
    __syncthreads();
    const float* Gp = g_M + ((size_t)b * HW + j0) * HW + i0;
    float*       Op = out + ((size_t)b * HW + j0) * HW + i0;
#pragma unroll 2
    for (int idx = t; idx < 128 * 32; idx += 256) {
        const int jj = idx >> 5, i4 = (idx & 31) * 4;
        float4 v = *(const float4*)(Gp + (size_t)jj * HW + i4);
        const float mj = mJ[jj], rj = rJ[jj];
        float4 o;
        o.x = __expf(2.f * v.x - mI[i4 + 0] - mj) * rI[i4 + 0] * rj;
        o.y = __expf(2.f * v.y - mI[i4 + 1] - mj) * rI[i4 + 1] * rj;
        o.z = __expf(2.f * v.z - mI[i4 + 2] - mj) * rI[i4 + 2] * rj;
        o.w = __expf(2.f * v.w - mI[i4 + 3] - mj) * rI[i4 + 3] * rj;
        *(float4*)(Op + (size_t)jj * HW + i4) = o;
    }
}

// ---------------- launch ----------------
extern "C" void kernel_launch(void* const* d_in, const int* in_sizes, int n_in,
                              void* d_out, int out_size) {
    const float* A  = (const float*)d_in[0];
    const float* Bf = (const float*)d_in[1];
    float* out = (float*)d_out;

    cudaFuncSetAttribute(k_gemm_mma, cudaFuncAttributeMaxDynamicSharedMemorySize, SMEM_DYN);

    k_init<<<(BATCH * HW + 255) / 256, 256>>>();
    k_transA<<<BATCH * CCH, 256>>>(A);
    k_splitB<<<(BATCH * CCH * HW) / 1024, 256>>>(Bf);
    dim3 ggrid(HW / TN, HW / TM, BATCH);
    k_gemm_mma<<<ggrid, 256, SMEM_DYN>>>();
    dim3 sgrid(HW / 128, BATCH);
    k_stats<<<sgrid, 256>>>();
    dim3 fgrid(HW / 128, HW / 128, BATCH);
    k_final<<<fgrid, 256>>>(out);
}